// round 6
// baseline (speedup 1.0000x reference)
#include <cuda_runtime.h>

#define NSUB 20
#define NE 500
#define NI 200
#define NB 3
#define T_SYN 201
#define TPAD 208          // taps padded to mult of 8 with zeros
#define KSTR 211          // ksh row stride: 211%32=19 -> s*19 mod 32 distinct for s<20
#define TMAX 100000

// K1 (GEMM) geometry: k axis = [e padded to 512 | i padded to 208] = 720
#define KTOT 720
#define ECOLS 512
#define NCHUNK 45
#define ECHUNK 32

// K2 (conv) geometry
#define TT 128
#define HALO TPAD
#define XROWS (TT + HALO)  // 336
#define RPAD 337           // 337%32=17 -> conflict-free per-channel rows

__device__ float g_kern[2 * NSUB * TPAD];   // [c][s][t]
__device__ float g_X[(size_t)TMAX * 40];    // [t][c*20+s]

typedef unsigned long long u64;

__device__ __forceinline__ u64 pk2(float a) {
    u64 r; asm("mov.b64 %0, {%1, %1};" : "=l"(r) : "f"(a)); return r;
}
__device__ __forceinline__ void fma2(u64& d, u64 a, u64 b) {
    asm("fma.rn.f32x2 %0, %1, %2, %0;" : "+l"(d) : "l"(a), "l"(b));
}

// ---------------------------------------------------------------------------
// K0: alpha-function kernel bank
// ---------------------------------------------------------------------------
__global__ void k0_kernels(const float* __restrict__ K_syn,
                           const float* __restrict__ tau_syn,
                           const float* __restrict__ delta_syn) {
    int idx = blockIdx.x * blockDim.x + threadIdx.x;
    if (idx >= 2 * NSUB * TPAD) return;
    int t = idx % TPAD;
    int s = (idx / TPAD) % NSUB;
    int c = idx / (TPAD * NSUB);
    float val = 0.f;
    if (t < T_SYN) {
        float ts = fmaxf((float)t - delta_syn[s * 2 + c], 0.f);
        #pragma unroll
        for (int b = 0; b < NB; b++) {
            float tau = expf(tau_syn[b * 2 + c]);
            float tt = ts / tau;
            val += K_syn[s * NB * 2 + b * 2 + c] * tt * expf(-tt);
        }
    }
    g_kern[idx] = val;
}

// ---------------------------------------------------------------------------
// K1: tall-skinny GEMM with packed f32x2 FMAs.
// 128 threads, 256 rows/CTA (2 rows/thread). All of C resident in smem as
// [k][s] (s-pairs -> direct 64-bit packed operands). S chunk register-staged
// (prefetch) then smem. Accumulators: 10 packed s-pairs per row per channel.
// ---------------------------------------------------------------------------
__global__ __launch_bounds__(128) void k1_gemm(const float* __restrict__ Se,
                                               const float* __restrict__ Si,
                                               const float* __restrict__ Ce,
                                               const float* __restrict__ Ci,
                                               int T) {
    extern __shared__ float sm1[];
    float* Csh = sm1;                  // [KTOT][20]  57.6 KB
    float* Ssh = sm1 + KTOT * 20;      // [256][20]   20.5 KB (pad 20 -> aligned float4 rows)

    int tid = threadIdx.x;
    int rbase = blockIdx.x * 256;

    // Load ALL of C once (coalesced on k)
    for (int idx = tid; idx < NSUB * KTOT; idx += 128) {
        int s = idx / KTOT, k = idx - s * KTOT;
        float v = 0.f;
        if (k < NE)                          v = Ce[s * NE + k];
        else if (k >= ECOLS && k < ECOLS+NI) v = Ci[s * NI + (k - ECOLS)];
        Csh[k * 20 + s] = v;
    }

    u64 accE0[10], accE1[10], accI0[10], accI1[10];
    #pragma unroll
    for (int p = 0; p < 10; p++) { accE0[p]=0ull; accE1[p]=0ull; accI0[p]=0ull; accI1[p]=0ull; }

    float st[32];

#define STAGE_LOAD(KB) do {                                                   \
    _Pragma("unroll")                                                         \
    for (int j = 0; j < 32; j++) {                                            \
        int idx = j * 128 + tid; int r = idx >> 4; int k = idx & 15;          \
        int kg = (KB) + k; int row = rbase + r; float v = 0.f;                \
        if (row < T) {                                                        \
            if (kg < NE)                           v = Se[(size_t)row*NE + kg];           \
            else if (kg >= ECOLS && kg < ECOLS+NI) v = Si[(size_t)row*NI + (kg-ECOLS)];   \
        }                                                                     \
        st[j] = v; } } while (0)

#define STAGE_STORE() do {                                                    \
    _Pragma("unroll")                                                         \
    for (int j = 0; j < 32; j++) {                                            \
        int idx = j * 128 + tid; int r = idx >> 4; int k = idx & 15;          \
        Ssh[r * 20 + k] = st[j]; } } while (0)

#define COMPUTE(KB, A0, A1) do {                                              \
    _Pragma("unroll")                                                         \
    for (int k4 = 0; k4 < 4; k4++) {                                          \
        float4 a0 = *(const float4*)&Ssh[tid * 20 + k4 * 4];                  \
        float4 a1 = *(const float4*)&Ssh[(tid + 128) * 20 + k4 * 4];          \
        float a0v[4] = {a0.x, a0.y, a0.z, a0.w};                              \
        float a1v[4] = {a1.x, a1.y, a1.z, a1.w};                              \
        _Pragma("unroll")                                                     \
        for (int m = 0; m < 4; m++) {                                         \
            int k = (KB) + k4 * 4 + m;                                        \
            u64 aa0 = pk2(a0v[m]); u64 aa1 = pk2(a1v[m]);                     \
            const ulonglong2* cp = (const ulonglong2*)&Csh[(size_t)k * 20];   \
            _Pragma("unroll")                                                 \
            for (int q = 0; q < 5; q++) {                                     \
                ulonglong2 c2 = cp[q];                                        \
                fma2(A0[2*q],   aa0, c2.x); fma2(A1[2*q],   aa1, c2.x);       \
                fma2(A0[2*q+1], aa0, c2.y); fma2(A1[2*q+1], aa1, c2.y);       \
            } } } } while (0)

    STAGE_LOAD(0);
    for (int cb = 0; cb < NCHUNK; cb++) {
        __syncthreads();           // previous chunk's compute done reading Ssh
        STAGE_STORE();
        __syncthreads();
        int kb = cb * 16;
        if (cb + 1 < NCHUNK) STAGE_LOAD(kb + 16);   // prefetch under compute
        if (cb < ECHUNK) COMPUTE(kb, accE0, accE1);
        else             COMPUTE(kb, accI0, accI1);
    }

    int row0 = rbase + tid, row1 = row0 + 128;
    if (row0 < T) {
        u64* d = (u64*)&g_X[(size_t)row0 * 40];
        #pragma unroll
        for (int p = 0; p < 10; p++) { d[p] = accE0[p]; d[10 + p] = accI0[p]; }
    }
    if (row1 < T) {
        u64* d = (u64*)&g_X[(size_t)row1 * 40];
        #pragma unroll
        for (int p = 0; p < 10; p++) { d[p] = accE1[p]; d[10 + p] = accI1[p]; }
    }
#undef STAGE_LOAD
#undef STAGE_STORE
#undef COMPUTE
}

// ---------------------------------------------------------------------------
// K2: depthwise causal FIR. Block dim3(20,16); thread (s,tg) -> 8 outputs.
// ksh stride 211 kills the 10-way bank conflict on tap loads.
// ---------------------------------------------------------------------------
__global__ __launch_bounds__(320) void k2_conv(float* __restrict__ out, int T) {
    extern __shared__ float sm[];
    float* Xsh = sm;                    // [40][RPAD]
    float* ksh = sm + 40 * RPAD;        // [40][KSTR]

    int tid = threadIdx.y * 20 + threadIdx.x;
    int t0 = blockIdx.x * TT;

    for (int idx = tid; idx < 40 * TPAD; idx += 320) {
        int row = idx / TPAD, t = idx - row * TPAD;
        ksh[row * KSTR + t] = g_kern[idx];
    }

    for (int idx = tid; idx < XROWS * 40; idx += 320) {
        int j = idx / 40, c2 = idx - j * 40;
        int tg = t0 - HALO + j;
        float v = (tg >= 0 && tg < T) ? g_X[(size_t)tg * 40 + c2] : 0.f;
        Xsh[c2 * RPAD + j] = v;
    }
    __syncthreads();

    int s = threadIdx.x, tg = threadIdx.y;
    float acc[8];
    #pragma unroll
    for (int r = 0; r < 8; r++) acc[r] = 0.f;

    int base_out = HALO + tg * 8;

    #pragma unroll
    for (int c = 0; c < 2; c++) {
        const float* xc = Xsh + (c * 20 + s) * RPAD;
        const float* kk = ksh + (c * 20 + s) * KSTR;
        #pragma unroll 2
        for (int kb = 0; kb < TPAD; kb += 8) {
            float kv[8];
            #pragma unroll
            for (int m = 0; m < 8; m++) kv[m] = kk[kb + m];
            float xw[15];
            int b = base_out - kb - 7;
            #pragma unroll
            for (int m = 0; m < 15; m++) xw[m] = xc[b + m];
            #pragma unroll
            for (int r = 0; r < 8; r++) {
                #pragma unroll
                for (int k = 0; k < 8; k++)
                    acc[r] = fmaf(kv[k], xw[r - k + 7], acc[r]);
            }
        }
    }

    #pragma unroll
    for (int r = 0; r < 8; r++) {
        int t = t0 + tg * 8 + r;
        if (t < T) out[(size_t)t * 20 + s] = acc[r];
    }
}

// ---------------------------------------------------------------------------
extern "C" void kernel_launch(void* const* d_in, const int* in_sizes, int n_in,
                              void* d_out, int out_size) {
    const float* Se        = (const float*)d_in[0];
    const float* Si        = (const float*)d_in[1];
    const float* Ce        = (const float*)d_in[2];
    const float* Ci        = (const float*)d_in[3];
    const float* K_syn     = (const float*)d_in[4];
    const float* tau_syn   = (const float*)d_in[5];
    const float* delta_syn = (const float*)d_in[6];
    float* out = (float*)d_out;

    int T = in_sizes[0] / NE;
    if (T > TMAX) T = TMAX;

    k0_kernels<<<(2 * NSUB * TPAD + 255) / 256, 256>>>(K_syn, tau_syn, delta_syn);

    int smem1 = (KTOT * 20 + 256 * 20) * (int)sizeof(float);   // 78,080 B
    cudaFuncSetAttribute(k1_gemm, cudaFuncAttributeMaxDynamicSharedMemorySize, smem1);
    k1_gemm<<<(T + 255) / 256, 128, smem1>>>(Se, Si, Ce, Ci, T);

    int smem2 = (40 * RPAD + 40 * KSTR) * (int)sizeof(float);  // 87,680 B
    cudaFuncSetAttribute(k2_conv, cudaFuncAttributeMaxDynamicSharedMemorySize, smem2);
    k2_conv<<<(T + TT - 1) / TT, dim3(20, 16), smem2>>>(out, T);
}

// round 8
// speedup vs baseline: 1.4110x; 1.4110x over previous
#include <cuda_runtime.h>
#include <cstdint>

#define NSUB 20
#define NE 500
#define NI 200
#define NB 3
#define T_SYN 201
#define TPAD 208          // taps padded to mult of 8 with zeros
#define KSTR 211          // ksh row stride: 211%32=19 -> conflict-free tap loads
#define TMAX 100000

// K1 geometry: unified C column axis = [e: 0..511 (500 real) | i: 512..719 (200 real)]
#define KTOT 720
#define IBASE 512
#define KE_CHUNKS 32      // 512 / 16
#define KI_CHUNKS 13      // 208 / 16

// K2 geometry
#define TT 128
#define HALO TPAD
#define XROWS (TT + HALO)  // 336
#define RPAD 337           // 337%32=17 -> conflict-free per-channel rows

__device__ float g_kern[2 * NSUB * TPAD];   // [c][s][t]
__device__ float g_X[(size_t)TMAX * 40];    // [t][c*20+s]

typedef unsigned long long u64;

__device__ __forceinline__ u64 pk2(float a) {
    u64 r; asm("mov.b64 %0, {%1, %1};" : "=l"(r) : "f"(a)); return r;
}
__device__ __forceinline__ void fma2(u64& d, u64 a, u64 b) {
    asm("fma.rn.f32x2 %0, %1, %2, %0;" : "+l"(d) : "l"(a), "l"(b));
}
__device__ __forceinline__ void cpasync16(uint32_t dst, const float* src, bool pred) {
    int sz = pred ? 16 : 0;
    asm volatile("cp.async.cg.shared.global [%0], [%1], 16, %2;"
                 :: "r"(dst), "l"(src), "r"(sz));
}

// ---------------------------------------------------------------------------
// K0: alpha-function kernel bank
// ---------------------------------------------------------------------------
__global__ void k0_kernels(const float* __restrict__ K_syn,
                           const float* __restrict__ tau_syn,
                           const float* __restrict__ delta_syn) {
    int idx = blockIdx.x * blockDim.x + threadIdx.x;
    if (idx >= 2 * NSUB * TPAD) return;
    int t = idx % TPAD;
    int s = (idx / TPAD) % NSUB;
    int c = idx / (TPAD * NSUB);
    float val = 0.f;
    if (t < T_SYN) {
        float ts = fmaxf((float)t - delta_syn[s * 2 + c], 0.f);
        #pragma unroll
        for (int b = 0; b < NB; b++) {
            float tau = expf(tau_syn[b * 2 + c]);
            float tt = ts / tau;
            val += K_syn[s * NB * 2 + b * 2 + c] * tt * expf(-tt);
        }
    }
    g_kern[idx] = val;
}

// ---------------------------------------------------------------------------
// K1: tall-skinny GEMM, f32x2 packed FMAs, cp.async double-buffered S tiles,
// PHASE-SPLIT accumulators (only 20 u64 accs live at a time -> no spills).
// 128 threads, 256 rows/CTA. Csh [k][20] -> subunit pairs are direct 16B
// ulonglong2 packed operands. S rows padded to 20 floats (conflict-free
// float4 reads: tid*20 mod 32 covers all banks per 8 lanes).
// ---------------------------------------------------------------------------
__global__ __launch_bounds__(128) void k1_gemm(const float* __restrict__ Se,
                                               const float* __restrict__ Si,
                                               const float* __restrict__ Ce,
                                               const float* __restrict__ Ci,
                                               int T) {
    extern __shared__ float sm1[];
    float* Csh = sm1;                     // [KTOT][20]   57.6 KB
    float* Ssh = sm1 + KTOT * 20;         // [2][256][20] 40.96 KB

    const int tid = threadIdx.x;
    const int rbase = blockIdx.x * 256;
    const uint32_t ssh_base = (uint32_t)__cvta_generic_to_shared(Ssh);

    // Load all of C once: layout [k][s]
    for (int idx = tid; idx < KTOT * NSUB; idx += 128) {
        int k = idx / NSUB, s = idx - k * NSUB;
        float v = 0.f;
        if (k < NE)                          v = Ce[s * NE + k];
        else if (k >= IBASE && k < IBASE+NI) v = Ci[s * NI + (k - IBASE)];
        Csh[k * NSUB + s] = v;
    }

    const int row0 = rbase + tid, row1 = row0 + 128;

// Issue one 256x16 S chunk into buffer BUF via cp.async (zfill for OOB).
#define ISSUE(SP, NC, KB, BUF) do {                                           \
    _Pragma("unroll")                                                         \
    for (int j = 0; j < 8; j++) {                                             \
        int idx = j * 128 + tid;                                              \
        int r = idx >> 2, kq = idx & 3;                                       \
        int kg = (KB) + kq * 4;                                               \
        int row = rbase + r;                                                  \
        bool pred = (row < T) && (kg + 3 < (NC));                             \
        const float* src = pred ? (SP) + (size_t)row * (NC) + kg : (SP);      \
        uint32_t dst = ssh_base + (uint32_t)(((BUF) * 256 + r) * 20 + kq * 4) * 4u; \
        cpasync16(dst, src, pred);                                            \
    }                                                                         \
    asm volatile("cp.async.commit_group;"); } while (0)

#define COMPUTE(BUF, CKB, A0, A1) do {                                        \
    const float* sb = Ssh + (BUF) * 256 * 20;                                 \
    _Pragma("unroll")                                                         \
    for (int k4 = 0; k4 < 4; k4++) {                                          \
        float4 a0 = *(const float4*)&sb[tid * 20 + k4 * 4];                   \
        float4 a1 = *(const float4*)&sb[(tid + 128) * 20 + k4 * 4];           \
        float a0v[4] = {a0.x, a0.y, a0.z, a0.w};                              \
        float a1v[4] = {a1.x, a1.y, a1.z, a1.w};                              \
        _Pragma("unroll")                                                     \
        for (int m = 0; m < 4; m++) {                                         \
            int kk = (CKB) + k4 * 4 + m;                                      \
            u64 aa0 = pk2(a0v[m]); u64 aa1 = pk2(a1v[m]);                     \
            const ulonglong2* cp = (const ulonglong2*)&Csh[kk * NSUB];        \
            _Pragma("unroll")                                                 \
            for (int q = 0; q < 5; q++) {                                     \
                ulonglong2 c2 = cp[q];                                        \
                fma2(A0[2*q],   aa0, c2.x); fma2(A1[2*q],   aa1, c2.x);       \
                fma2(A0[2*q+1], aa0, c2.y); fma2(A1[2*q+1], aa1, c2.y);       \
            } } } } while (0)

// One phase: NCH chunks, own accumulators, store to g_X at column offset OFF.
#define PHASE(SP, NC, NCH, CBASE, OFF) do {                                   \
    u64 acc0[10], acc1[10];                                                   \
    _Pragma("unroll")                                                         \
    for (int p = 0; p < 10; p++) { acc0[p] = 0ull; acc1[p] = 0ull; }          \
    ISSUE(SP, NC, 0, 0);                                                      \
    for (int cb = 0; cb < (NCH); cb++) {                                      \
        if (cb + 1 < (NCH)) {                                                 \
            ISSUE(SP, NC, (cb + 1) * 16, (cb + 1) & 1);                       \
            asm volatile("cp.async.wait_group 1;");                           \
        } else {                                                              \
            asm volatile("cp.async.wait_group 0;");                           \
        }                                                                     \
        __syncthreads();                                                      \
        COMPUTE(cb & 1, (CBASE) + cb * 16, acc0, acc1);                       \
        __syncthreads();                                                      \
    }                                                                         \
    if (row0 < T) {                                                           \
        u64* d = (u64*)&g_X[(size_t)row0 * 40 + (OFF)];                       \
        _Pragma("unroll")                                                     \
        for (int p = 0; p < 10; p++) d[p] = acc0[p];                          \
    }                                                                         \
    if (row1 < T) {                                                           \
        u64* d = (u64*)&g_X[(size_t)row1 * 40 + (OFF)];                       \
        _Pragma("unroll")                                                     \
        for (int p = 0; p < 10; p++) d[p] = acc1[p];                          \
    } } while (0)

    PHASE(Se, NE, KE_CHUNKS, 0,     0);
    PHASE(Si, NI, KI_CHUNKS, IBASE, 20);

#undef ISSUE
#undef COMPUTE
#undef PHASE
}

// ---------------------------------------------------------------------------
// K2: depthwise causal FIR. Block dim3(20,16); thread (s,tg) -> 8 outputs.
// ksh stride 211 -> conflict-free tap loads (s*211 mod 32 distinct for s<20).
// ---------------------------------------------------------------------------
__global__ __launch_bounds__(320) void k2_conv(float* __restrict__ out, int T) {
    extern __shared__ float sm[];
    float* Xsh = sm;                    // [40][RPAD]
    float* ksh = sm + 40 * RPAD;        // [40][KSTR]

    int tid = threadIdx.y * 20 + threadIdx.x;
    int t0 = blockIdx.x * TT;

    for (int idx = tid; idx < 40 * TPAD; idx += 320) {
        int row = idx / TPAD, t = idx - row * TPAD;
        ksh[row * KSTR + t] = g_kern[idx];
    }

    for (int idx = tid; idx < XROWS * 40; idx += 320) {
        int j = idx / 40, c2 = idx - j * 40;
        int tg = t0 - HALO + j;
        float v = (tg >= 0 && tg < T) ? g_X[(size_t)tg * 40 + c2] : 0.f;
        Xsh[c2 * RPAD + j] = v;
    }
    __syncthreads();

    int s = threadIdx.x, tg = threadIdx.y;
    float acc[8];
    #pragma unroll
    for (int r = 0; r < 8; r++) acc[r] = 0.f;

    int base_out = HALO + tg * 8;

    #pragma unroll
    for (int c = 0; c < 2; c++) {
        const float* xc = Xsh + (c * 20 + s) * RPAD;
        const float* kk = ksh + (c * 20 + s) * KSTR;
        #pragma unroll 2
        for (int kb = 0; kb < TPAD; kb += 8) {
            float kv[8];
            #pragma unroll
            for (int m = 0; m < 8; m++) kv[m] = kk[kb + m];
            float xw[15];
            int b = base_out - kb - 7;
            #pragma unroll
            for (int m = 0; m < 15; m++) xw[m] = xc[b + m];
            #pragma unroll
            for (int r = 0; r < 8; r++) {
                #pragma unroll
                for (int k = 0; k < 8; k++)
                    acc[r] = fmaf(kv[k], xw[r - k + 7], acc[r]);
            }
        }
    }

    #pragma unroll
    for (int r = 0; r < 8; r++) {
        int t = t0 + tg * 8 + r;
        if (t < T) out[(size_t)t * 20 + s] = acc[r];
    }
}

// ---------------------------------------------------------------------------
extern "C" void kernel_launch(void* const* d_in, const int* in_sizes, int n_in,
                              void* d_out, int out_size) {
    const float* Se        = (const float*)d_in[0];
    const float* Si        = (const float*)d_in[1];
    const float* Ce        = (const float*)d_in[2];
    const float* Ci        = (const float*)d_in[3];
    const float* K_syn     = (const float*)d_in[4];
    const float* tau_syn   = (const float*)d_in[5];
    const float* delta_syn = (const float*)d_in[6];
    float* out = (float*)d_out;

    int T = in_sizes[0] / NE;
    if (T > TMAX) T = TMAX;

    k0_kernels<<<(2 * NSUB * TPAD + 255) / 256, 256>>>(K_syn, tau_syn, delta_syn);

    int smem1 = (KTOT * 20 + 2 * 256 * 20) * (int)sizeof(float);  // 98,560 B
    cudaFuncSetAttribute(k1_gemm, cudaFuncAttributeMaxDynamicSharedMemorySize, smem1);
    k1_gemm<<<(T + 255) / 256, 128, smem1>>>(Se, Si, Ce, Ci, T);

    int smem2 = (40 * RPAD + 40 * KSTR) * (int)sizeof(float);     // 87,680 B
    cudaFuncSetAttribute(k2_conv, cudaFuncAttributeMaxDynamicSharedMemorySize, smem2);
    k2_conv<<<(T + TT - 1) / TT, dim3(20, 16), smem2>>>(out, T);
}